// round 14
// baseline (speedup 1.0000x reference)
#include <cuda_runtime.h>
#include <cuda_fp16.h>
#include <math.h>
#include <stdint.h>

// Problem constants
#define T_  256
#define B_  64
#define I_  1024
#define L_  2
#define G_  4
#define H_  1024
#define R_  16

#define N_TOT  (G_ * H_)
#define K_HALF 1024

// GEMM config: grid (32 M-tiles, 8 k-splits), 256 thr, 2 CTA/SM
#define KS     8
#define KSLICE 256
#define MT     128
#define NSTEP  (KSLICE / 16)
#define PF     3

// Scratch: single accumulated pre buffer (1 MB). Device globals boot zeroed;
// gates re-zeros after reading, so every call (and graph replay) sees zeros.
__device__ float g_pre1[N_TOT * B_];       // [m][b]
__device__ float g_u[2 * G_ * R_ * B_];    // [src][g][r][b]  (b fast)

#define SWZ(o) ((o) ^ (((o) >> 3) & 0x70))

__device__ __forceinline__ uint32_t smem_u32(const void* p) {
    uint32_t a;
    asm("{ .reg .u64 t; cvta.to.shared.u64 t, %1; cvt.u32.u64 %0, t; }" : "=r"(a) : "l"(p));
    return a;
}
__device__ __forceinline__ uint32_t pack_h2(float a, float b) {
    __half2 h = __floats2half2_rn(a, b);
    return *(uint32_t*)&h;
}
__device__ __forceinline__ void ldsm4(uint32_t* r, uint32_t addr) {
    asm volatile("ldmatrix.sync.aligned.m8n8.x4.shared.b16 {%0,%1,%2,%3}, [%4];"
                 : "=r"(r[0]), "=r"(r[1]), "=r"(r[2]), "=r"(r[3]) : "r"(addr));
}
__device__ __forceinline__ void mma_fp16(float* d, const uint32_t* a, uint32_t b0, uint32_t b1) {
    asm volatile("mma.sync.aligned.m16n8k16.row.col.f32.f16.f16.f32 "
                 "{%0,%1,%2,%3}, {%4,%5,%6,%7}, {%8,%9}, {%0,%1,%2,%3};"
                 : "+f"(d[0]), "+f"(d[1]), "+f"(d[2]), "+f"(d[3])
                 : "r"(a[0]), "r"(a[1]), "r"(a[2]), "r"(a[3]), "r"(b0), "r"(b1));
}
__device__ __forceinline__ void red2(float* p, float a, float b) {
    asm volatile("red.global.add.v2.f32 [%0], {%1, %2};"
                 :: "l"(p), "f"(a), "f"(b) : "memory");
}

// ---------------------------------------------------------------------------
// Fused kernel: (a) rank-16 LoRA projections in fp32 (hidden under the W
// stream), (b) HMMA split-K GEMM, single-pass fp16, fp32 accumulate,
// (c) epilogue accumulates into the shared pre buffer via red.add.v2.f32.
// ---------------------------------------------------------------------------
__global__ void __launch_bounds__(256, 2)
gemm_mma_kernel(const float* __restrict__ x, const float* __restrict__ h0,
                const float* __restrict__ W_x, const float* __restrict__ W_h,
                const float* __restrict__ A_x, const float* __restrict__ A_h,
                int l)
{
    __shared__ __align__(1024) uint8_t sx_hi[8192];   // x chunk: 64 n x 64 k fp16, SWZ

    const int tid  = threadIdx.x;
    const int wid  = tid >> 5;
    const int lane = tid & 31;
    const int ks   = blockIdx.y;
    const int m0   = blockIdx.x * MT;

    const float* Wbase;
    const float* vbase;
    int koff;
    if (ks < 4) { Wbase = W_x + (size_t)l * N_TOT * K_HALF; vbase = x;
                  koff = ks * KSLICE; }
    else        { Wbase = W_h + (size_t)l * N_TOT * K_HALF; vbase = h0 + (size_t)l * B_ * H_;
                  koff = (ks - 4) * KSLICE; }

    const int g = lane >> 2;
    const int q = lane & 3;

    const float* WA = Wbase + (size_t)(m0 + wid * 16 + g) * K_HALF + koff;
    const float* WB = WA + 8 * (size_t)K_HALF;

    // -------- issue first PF steps of W loads immediately --------
    float2 wbufA0[PF], wbufA1[PF], wbufB0[PF], wbufB1[PF];
#pragma unroll
    for (int s = 0; s < PF; ++s) {
        const int kk = s * 16 + 2 * q;
        wbufA0[s] = *(const float2*)(WA + kk);
        wbufA1[s] = *(const float2*)(WA + kk + 8);
        wbufB0[s] = *(const float2*)(WB + kk);
        wbufB1[s] = *(const float2*)(WB + kk + 8);
    }

    // -------- LoRA projections (fp32 exact; while W loads are in flight) ----
    {
        const uint32_t wg = ((uint32_t)blockIdx.y * 32u + blockIdx.x) * 8u + wid;
#pragma unroll
        for (int t = 0; t < 2; ++t) {
            const uint32_t task = wg * 2u + t;      // 0..4095
            const int src  = task >> 11;
            const int rem  = task & 2047;
            const int gg   = rem >> 9;
            const int rem2 = rem & 511;
            const int b    = rem2 >> 3;
            const int rp   = rem2 & 7;

            const float* vec = (src == 0) ? (x + (size_t)b * I_)
                                          : (h0 + (size_t)l * B_ * H_ + (size_t)b * H_);
            const float* A = ((src == 0) ? A_x : A_h) + ((size_t)(l * G_ + gg)) * R_ * K_HALF;
            const float4* v4 = (const float4*)vec;
            const float4* a0 = (const float4*)(A + (size_t)(rp * 2) * K_HALF);
            const float4* a1 = (const float4*)(A + (size_t)(rp * 2 + 1) * K_HALF);

            float acc0 = 0.f, acc1 = 0.f;
#pragma unroll
            for (int j = 0; j < 8; ++j) {
                const int i4 = j * 32 + lane;
                float4 v = v4[i4];
                float4 a = a0[i4];
                float4 c = a1[i4];
                acc0 += v.x * a.x + v.y * a.y + v.z * a.z + v.w * a.w;
                acc1 += v.x * c.x + v.y * c.y + v.z * c.z + v.w * c.w;
            }
#pragma unroll
            for (int off = 16; off > 0; off >>= 1) {
                acc0 += __shfl_down_sync(0xffffffffu, acc0, off);
                acc1 += __shfl_down_sync(0xffffffffu, acc1, off);
            }
            if (lane == 0) {
                float* u = &g_u[((size_t)(src * G_ + gg) * R_) * B_ + b];
                u[(size_t)(rp * 2) * B_]     = acc0;
                u[(size_t)(rp * 2 + 1) * B_] = acc1;
            }
        }
    }

    // -------- x staging geometry --------
    const int xn = tid >> 2;
    const int xq = tid & 3;
    const float* Xsrc = vbase + (size_t)xn * K_HALF + koff + xq * 16;
    uint32_t st_off[4];
#pragma unroll
    for (int j = 0; j < 4; ++j) {
        uint32_t o = (uint32_t)xn * 128u + (uint32_t)xq * 32u + (uint32_t)j * 8u;
        st_off[j] = SWZ(o);
    }

    // ldmatrix lane geometry
    const int lm_row  = 8 * ((lane >> 4) & 1) + (lane & 7);
    const int lm_kb   = ((lane >> 3) & 1) * 16;
    const int cswz    = (lane & 7) << 4;
    const uint32_t rowoff = (uint32_t)lm_row * 128u;
    const uint32_t hi_base = smem_u32(sx_hi);

    float acc[8][4];
#pragma unroll
    for (int t = 0; t < 8; ++t)
#pragma unroll
        for (int j = 0; j < 4; ++j) acc[t][j] = 0.f;

#pragma unroll
    for (int step = 0; step < NSTEP; ++step) {
        if ((step & 3) == 0) {                 // stage next 64-k chunk of x
            if (step) __syncthreads();
            const float4* s4 = (const float4*)(Xsrc + (step >> 2) * 64);
#pragma unroll
            for (int j = 0; j < 4; ++j) {
                float4 f = s4[j];
                *(uint2*)(sx_hi + st_off[j]) =
                    make_uint2(pack_h2(f.x, f.y), pack_h2(f.z, f.w));
            }
            __syncthreads();
        }

        const int cur = step % PF;             // static under full unroll

        uint32_t a_f[4];
        a_f[0] = pack_h2(wbufA0[cur].x, wbufA0[cur].y);
        a_f[1] = pack_h2(wbufB0[cur].x, wbufB0[cur].y);
        a_f[2] = pack_h2(wbufA1[cur].x, wbufA1[cur].y);
        a_f[3] = pack_h2(wbufB1[cur].x, wbufB1[cur].y);

        if (step + PF < NSTEP) {               // refill the freed slot
            const int kk = (step + PF) * 16 + 2 * q;
            wbufA0[cur] = *(const float2*)(WA + kk);
            wbufA1[cur] = *(const float2*)(WA + kk + 8);
            wbufB0[cur] = *(const float2*)(WB + kk);
            wbufB1[cur] = *(const float2*)(WB + kk + 8);
        }

        const int kb = lm_kb + (step & 3) * 32;
        const uint32_t koffsw = (uint32_t)(kb ^ cswz);

#pragma unroll
        for (int tp = 0; tp < 4; ++tp) {
            const uint32_t off = rowoff + (uint32_t)tp * 2048u + koffsw;
            uint32_t bh[4];
            ldsm4(bh, hi_base + off);
            mma_fp16(acc[2 * tp],     a_f, bh[0], bh[1]);
            mma_fp16(acc[2 * tp + 1], a_f, bh[2], bh[3]);
        }
    }

    // epilogue: accumulate into shared pre buffer (REDG, no K copies)
    {
        float* dst0 = &g_pre1[((size_t)(m0 + wid * 16 + g)) * B_];
        float* dst8 = dst0 + 8 * B_;
#pragma unroll
        for (int t = 0; t < 8; ++t) {
            red2(dst0 + t * 8 + 2 * q, acc[t][0], acc[t][1]);
            red2(dst8 + t * 8 + 2 * q, acc[t][2], acc[t][3]);
        }
    }
}

// ---------------------------------------------------------------------------
// Gates: one block per TWO h values (grid 512). Thread = (gate, b).
// Reads the single accumulated pre value, then RE-ZEROS it (keeps the buffer
// zero for the next layer / next graph replay).
// ---------------------------------------------------------------------------
__global__ void __launch_bounds__(256)
gates_kernel(const float* __restrict__ b_x,
             const float* __restrict__ b_h,
             const float* __restrict__ B_x,
             const float* __restrict__ B_h,
             const float* __restrict__ c0,
             float* __restrict__ out,
             int l)
{
    __shared__ float sp[G_][2][B_];

    const int h0 = blockIdx.x * 2;
    const int gg = threadIdx.x >> 6;
    const int b  = threadIdx.x & 63;

    float s0 = b_x[(l * G_ + gg) * H_ + h0]     + b_h[(l * G_ + gg) * H_ + h0];
    float s1 = b_x[(l * G_ + gg) * H_ + h0 + 1] + b_h[(l * G_ + gg) * H_ + h0 + 1];

    // single accumulated partials; read then re-zero
    float* pp = &g_pre1[((size_t)gg * H_ + h0) * B_ + b];
    s0 += pp[0];
    s1 += pp[B_];
    pp[0]  = 0.f;
    pp[B_] = 0.f;

    const float* Bx0 = B_x + ((size_t)((l * G_ + gg) * H_) + h0) * R_;
    const float* Bh0 = B_h + ((size_t)((l * G_ + gg) * H_) + h0) * R_;
    const float* ux = g_u + ((size_t)(0 * G_ + gg) * R_) * B_ + b;
    const float* uh = g_u + ((size_t)(1 * G_ + gg) * R_) * B_ + b;
#pragma unroll
    for (int r = 0; r < R_; ++r) {
        const float u = ux[(size_t)r * B_];
        s0 += Bx0[r] * u;
        s1 += Bx0[R_ + r] * u;
    }
#pragma unroll
    for (int r = 0; r < R_; ++r) {
        const float u = uh[(size_t)r * B_];
        s0 += Bh0[r] * u;
        s1 += Bh0[R_ + r] * u;
    }

    sp[gg][0][b] = s0;
    sp[gg][1][b] = s1;
    __syncthreads();

    if (threadIdx.x < 128) {
        const int bb = threadIdx.x & 63;
        const int hh = threadIdx.x >> 6;
        const int h  = h0 + hh;

        const float i_t = 1.f / (1.f + expf(-sp[0][hh][bb]));
        const float f_t = 1.f / (1.f + expf(-sp[1][hh][bb]));
        const float g_t = tanhf(sp[2][hh][bb]);
        const float o_t = 1.f / (1.f + expf(-sp[3][hh][bb]));

        const float cv   = c0[(size_t)l * B_ * H_ + (size_t)bb * H_ + h];
        const float cnew = f_t * cv + i_t * g_t;
        const float hnew = o_t * tanhf(cnew);

        const size_t idx = (size_t)bb * H_ + h;
        out[(size_t)B_ * H_ * (1 + l) + idx] = hnew;   // h_t[l]
        out[(size_t)B_ * H_ * (3 + l) + idx] = cnew;   // c_t[l]
        if (l == 1)
            out[idx] = hnew;                           // out == h_t[1]
    }
}

// ---------------------------------------------------------------------------
extern "C" void kernel_launch(void* const* d_in, const int* in_sizes, int n_in,
                              void* d_out, int out_size)
{
    const float* input_seq = (const float*)d_in[0];
    const float* h0        = (const float*)d_in[1];
    const float* c0        = (const float*)d_in[2];
    const float* W_x       = (const float*)d_in[3];
    const float* W_h       = (const float*)d_in[4];
    const float* b_x       = (const float*)d_in[5];
    const float* b_h       = (const float*)d_in[6];
    const float* A_x       = (const float*)d_in[7];
    const float* B_x       = (const float*)d_in[8];
    const float* A_h       = (const float*)d_in[9];
    const float* B_h       = (const float*)d_in[10];
    float* out = (float*)d_out;

    const float* x_last = input_seq + (size_t)(T_ - 1) * B_ * I_;

    for (int l = 0; l < L_; ++l) {
        const float* x = (l == 0) ? x_last : (out + (size_t)B_ * H_);  // h_t[0]

        gemm_mma_kernel<<<dim3(N_TOT / MT, KS), 256>>>(x, h0, W_x, W_h, A_x, A_h, l);
        gates_kernel<<<H_ / 2, 256>>>(b_x, b_h, B_x, B_h, c0, out, l);
    }
}

// round 15
// speedup vs baseline: 1.1413x; 1.1413x over previous
#include <cuda_runtime.h>
#include <cuda_fp16.h>
#include <math.h>
#include <stdint.h>

// Problem constants
#define T_  256
#define B_  64
#define I_  1024
#define L_  2
#define G_  4
#define H_  1024
#define R_  16

#define N_TOT  (G_ * H_)
#define K_HALF 1024

// GEMM config: grid (32 M-tiles, 8 k-splits), 256 thr, 2 CTA/SM
// (all 256 CTAs co-resident -> in-kernel spin cannot deadlock)
#define KS     8
#define KSLICE 256
#define MT     128
#define NSTEP  (KSLICE / 16)
#define PF     3

// Scratch
__device__ float    g_pre[KS * N_TOT * B_];   // [ks][m][b]  8 MB
__device__ float    g_u[2 * G_ * B_ * R_];    // [src][g][b][r]  (r fast)
__device__ unsigned g_ucnt;                   // monotonic LoRA-publish counter

#define SWZ(o) ((o) ^ (((o) >> 3) & 0x70))

__device__ __forceinline__ uint32_t smem_u32(const void* p) {
    uint32_t a;
    asm("{ .reg .u64 t; cvta.to.shared.u64 t, %1; cvt.u32.u64 %0, t; }" : "=r"(a) : "l"(p));
    return a;
}
__device__ __forceinline__ uint32_t pack_h2(float a, float b) {
    __half2 h = __floats2half2_rn(a, b);
    return *(uint32_t*)&h;
}
__device__ __forceinline__ void ldsm4(uint32_t* r, uint32_t addr) {
    asm volatile("ldmatrix.sync.aligned.m8n8.x4.shared.b16 {%0,%1,%2,%3}, [%4];"
                 : "=r"(r[0]), "=r"(r[1]), "=r"(r[2]), "=r"(r[3]) : "r"(addr));
}
__device__ __forceinline__ void mma_fp16(float* d, const uint32_t* a, uint32_t b0, uint32_t b1) {
    asm volatile("mma.sync.aligned.m16n8k16.row.col.f32.f16.f16.f32 "
                 "{%0,%1,%2,%3}, {%4,%5,%6,%7}, {%8,%9}, {%0,%1,%2,%3};"
                 : "+f"(d[0]), "+f"(d[1]), "+f"(d[2]), "+f"(d[3])
                 : "r"(a[0]), "r"(a[1]), "r"(a[2]), "r"(a[3]), "r"(b0), "r"(b1));
}

// ---------------------------------------------------------------------------
// Fused kernel: (a) rank-16 LoRA projections (fp32, hidden under the W
// stream), (b) HMMA split-K GEMM (fp16 single-pass), (c) ks=0 CTAs append
// TWO extra k16 MMA steps that fold the LoRA B-contraction (Bx·ux + Bh·uh)
// into their partials via tensor cores.
// ---------------------------------------------------------------------------
__global__ void __launch_bounds__(256, 2)
gemm_mma_kernel(const float* __restrict__ x, const float* __restrict__ h0,
                const float* __restrict__ W_x, const float* __restrict__ W_h,
                const float* __restrict__ A_x, const float* __restrict__ A_h,
                const float* __restrict__ B_x, const float* __restrict__ B_h,
                int l)
{
    __shared__ __align__(1024) uint8_t sx_hi[8192];   // x chunk: 64 n x 64 k fp16, SWZ
    __shared__ unsigned s_uold;

    const int tid  = threadIdx.x;
    const int wid  = tid >> 5;
    const int lane = tid & 31;
    const int ks   = blockIdx.y;
    const int m0   = blockIdx.x * MT;

    const float* Wbase;
    const float* vbase;
    int koff;
    if (ks < 4) { Wbase = W_x + (size_t)l * N_TOT * K_HALF; vbase = x;
                  koff = ks * KSLICE; }
    else        { Wbase = W_h + (size_t)l * N_TOT * K_HALF; vbase = h0 + (size_t)l * B_ * H_;
                  koff = (ks - 4) * KSLICE; }

    const int g = lane >> 2;
    const int q = lane & 3;

    const float* WA = Wbase + (size_t)(m0 + wid * 16 + g) * K_HALF + koff;
    const float* WB = WA + 8 * (size_t)K_HALF;

    // -------- issue first PF steps of W loads immediately --------
    float2 wbufA0[PF], wbufA1[PF], wbufB0[PF], wbufB1[PF];
#pragma unroll
    for (int s = 0; s < PF; ++s) {
        const int kk = s * 16 + 2 * q;
        wbufA0[s] = *(const float2*)(WA + kk);
        wbufA1[s] = *(const float2*)(WA + kk + 8);
        wbufB0[s] = *(const float2*)(WB + kk);
        wbufB1[s] = *(const float2*)(WB + kk + 8);
    }

    // -------- LoRA projections (fp32; while W loads are in flight) --------
    {
        const uint32_t wg = ((uint32_t)blockIdx.y * 32u + blockIdx.x) * 8u + wid;
#pragma unroll
        for (int t = 0; t < 2; ++t) {
            const uint32_t task = wg * 2u + t;      // 0..4095
            const int src  = task >> 11;
            const int rem  = task & 2047;
            const int gg   = rem >> 9;
            const int rem2 = rem & 511;
            const int b    = rem2 >> 3;
            const int rp   = rem2 & 7;

            const float* vec = (src == 0) ? (x + (size_t)b * I_)
                                          : (h0 + (size_t)l * B_ * H_ + (size_t)b * H_);
            const float* A = ((src == 0) ? A_x : A_h) + ((size_t)(l * G_ + gg)) * R_ * K_HALF;
            const float4* v4 = (const float4*)vec;
            const float4* a0 = (const float4*)(A + (size_t)(rp * 2) * K_HALF);
            const float4* a1 = (const float4*)(A + (size_t)(rp * 2 + 1) * K_HALF);

            float acc0 = 0.f, acc1 = 0.f;
#pragma unroll
            for (int j = 0; j < 8; ++j) {
                const int i4 = j * 32 + lane;
                float4 v = v4[i4];
                float4 a = a0[i4];
                float4 c = a1[i4];
                acc0 += v.x * a.x + v.y * a.y + v.z * a.z + v.w * a.w;
                acc1 += v.x * c.x + v.y * c.y + v.z * c.z + v.w * c.w;
            }
#pragma unroll
            for (int off = 16; off > 0; off >>= 1) {
                acc0 += __shfl_down_sync(0xffffffffu, acc0, off);
                acc1 += __shfl_down_sync(0xffffffffu, acc1, off);
            }
            if (lane == 0) {
                float* u = &g_u[((size_t)(src * G_ + gg) * B_ + b) * R_ + rp * 2];
                u[0] = acc0;
                u[1] = acc1;
            }
        }
        __threadfence();
        __syncthreads();
        if (tid == 0) s_uold = atomicAdd(&g_ucnt, 1u);   // publish
    }

    // -------- x staging geometry --------
    const int xn = tid >> 2;
    const int xq = tid & 3;
    const float* Xsrc = vbase + (size_t)xn * K_HALF + koff + xq * 16;
    uint32_t st_off[4];
#pragma unroll
    for (int j = 0; j < 4; ++j) {
        uint32_t o = (uint32_t)xn * 128u + (uint32_t)xq * 32u + (uint32_t)j * 8u;
        st_off[j] = SWZ(o);
    }

    // ldmatrix lane geometry
    const int lm_row  = 8 * ((lane >> 4) & 1) + (lane & 7);
    const int lm_kb   = ((lane >> 3) & 1) * 16;
    const int cswz    = (lane & 7) << 4;
    const uint32_t rowoff = (uint32_t)lm_row * 128u;
    const uint32_t hi_base = smem_u32(sx_hi);

    float acc[8][4];
#pragma unroll
    for (int t = 0; t < 8; ++t)
#pragma unroll
        for (int j = 0; j < 4; ++j) acc[t][j] = 0.f;

#pragma unroll
    for (int step = 0; step < NSTEP; ++step) {
        if ((step & 3) == 0) {                 // stage next 64-k chunk of x
            if (step) __syncthreads();
            const float4* s4 = (const float4*)(Xsrc + (step >> 2) * 64);
#pragma unroll
            for (int j = 0; j < 4; ++j) {
                float4 f = s4[j];
                *(uint2*)(sx_hi + st_off[j]) =
                    make_uint2(pack_h2(f.x, f.y), pack_h2(f.z, f.w));
            }
            __syncthreads();
        }

        const int cur = step % PF;             // static under full unroll

        uint32_t a_f[4];
        a_f[0] = pack_h2(wbufA0[cur].x, wbufA0[cur].y);
        a_f[1] = pack_h2(wbufB0[cur].x, wbufB0[cur].y);
        a_f[2] = pack_h2(wbufA1[cur].x, wbufA1[cur].y);
        a_f[3] = pack_h2(wbufB1[cur].x, wbufB1[cur].y);

        if (step + PF < NSTEP) {               // refill the freed slot
            const int kk = (step + PF) * 16 + 2 * q;
            wbufA0[cur] = *(const float2*)(WA + kk);
            wbufA1[cur] = *(const float2*)(WA + kk + 8);
            wbufB0[cur] = *(const float2*)(WB + kk);
            wbufB1[cur] = *(const float2*)(WB + kk + 8);
        }

        const int kb = lm_kb + (step & 3) * 32;
        const uint32_t koffsw = (uint32_t)(kb ^ cswz);

#pragma unroll
        for (int tp = 0; tp < 4; ++tp) {
            const uint32_t off = rowoff + (uint32_t)tp * 2048u + koffsw;
            uint32_t bh[4];
            ldsm4(bh, hi_base + off);
            mma_fp16(acc[2 * tp],     a_f, bh[0], bh[1]);
            mma_fp16(acc[2 * tp + 1], a_f, bh[2], bh[3]);
        }
    }

    // ======== ks==0: fold LoRA B-contraction via TWO extra k16 steps ========
    if (ks == 0) {
        // wait until all 256 CTAs of this launch have published their u
        if (tid == 0) {
            const unsigned tgt = ((s_uold / 256u) + 1u) * 256u;
            while (*((volatile unsigned*)&g_ucnt) < tgt) __nanosleep(32);
        }
        __syncthreads();
        __threadfence();

        // stage u' tile: 64 rows (b) x 32 k fp16 = [ux r0-15 | uh r0-15], SWZ
        {
            const int gatec = m0 >> 10;                 // CTA-uniform gate
            const int b    = tid >> 2;
            const int part = tid & 3;
            const int src  = part >> 1;
            const int roff = (part & 1) * 8;
            const float* up = g_u + ((size_t)(src * G_ + gatec) * B_ + b) * R_ + roff;
            float4 f0 = *(const float4*)up;
            float4 f1 = *(const float4*)(up + 4);
            const uint32_t base = (uint32_t)b * 128u + (uint32_t)(src * 32 + roff * 2);
            const uint32_t sw = SWZ(base);
            *(uint2*)(sx_hi + sw)     = make_uint2(pack_h2(f0.x, f0.y), pack_h2(f0.z, f0.w));
            *(uint2*)(sx_hi + sw + 8) = make_uint2(pack_h2(f1.x, f1.y), pack_h2(f1.z, f1.w));
        }
        __syncthreads();

        const float* BxP = B_x + ((size_t)l * N_TOT + m0 + wid * 16 + g) * R_;
        const float* BhP = B_h + ((size_t)l * N_TOT + m0 + wid * 16 + g) * R_;

#pragma unroll
        for (int e = 0; e < 2; ++e) {
            const float* BP = e ? BhP : BxP;
            float2 a0 = *(const float2*)(BP + 2 * q);
            float2 a1 = *(const float2*)(BP + 2 * q + 8);
            float2 b0 = *(const float2*)(BP + 8 * R_ + 2 * q);
            float2 b1 = *(const float2*)(BP + 8 * R_ + 2 * q + 8);
            uint32_t a_f[4];
            a_f[0] = pack_h2(a0.x, a0.y);
            a_f[1] = pack_h2(b0.x, b0.y);
            a_f[2] = pack_h2(a1.x, a1.y);
            a_f[3] = pack_h2(b1.x, b1.y);

            const uint32_t koffsw = (uint32_t)((lm_kb + e * 32) ^ cswz);
#pragma unroll
            for (int tp = 0; tp < 4; ++tp) {
                const uint32_t off = rowoff + (uint32_t)tp * 2048u + koffsw;
                uint32_t bh[4];
                ldsm4(bh, hi_base + off);
                mma_fp16(acc[2 * tp],     a_f, bh[0], bh[1]);
                mma_fp16(acc[2 * tp + 1], a_f, bh[2], bh[3]);
            }
        }
    }

    // -------- epilogue: store partials --------
    float* base0 = &g_pre[((size_t)ks * N_TOT + m0 + wid * 16 + g) * B_];
    float* base8 = base0 + 8 * B_;
#pragma unroll
    for (int t = 0; t < 8; ++t) {
        *(float2*)(base0 + t * 8 + 2 * q) = make_float2(acc[t][0], acc[t][1]);
        *(float2*)(base8 + t * 8 + 2 * q) = make_float2(acc[t][2], acc[t][3]);
    }
}

// ---------------------------------------------------------------------------
// Gates (lean): one block per TWO h values (grid 512). Thread = (gate, b).
// Only bias + 8 split-K partials + activations — LoRA already folded by GEMM.
// ---------------------------------------------------------------------------
__global__ void __launch_bounds__(256)
gates_kernel(const float* __restrict__ b_x,
             const float* __restrict__ b_h,
             const float* __restrict__ c0,
             float* __restrict__ out,
             int l)
{
    __shared__ float sp[G_][2][B_];

    const int h0 = blockIdx.x * 2;
    const int gg = threadIdx.x >> 6;
    const int b  = threadIdx.x & 63;

    float s0 = b_x[(l * G_ + gg) * H_ + h0]     + b_h[(l * G_ + gg) * H_ + h0];
    float s1 = b_x[(l * G_ + gg) * H_ + h0 + 1] + b_h[(l * G_ + gg) * H_ + h0 + 1];

    const float* p = &g_pre[((size_t)gg * H_ + h0) * B_ + b];
#pragma unroll
    for (int ks = 0; ks < KS; ++ks) {
        s0 += p[(size_t)ks * N_TOT * B_];
        s1 += p[(size_t)ks * N_TOT * B_ + B_];
    }

    sp[gg][0][b] = s0;
    sp[gg][1][b] = s1;
    __syncthreads();

    if (threadIdx.x < 128) {
        const int bb = threadIdx.x & 63;
        const int hh = threadIdx.x >> 6;
        const int h  = h0 + hh;

        const float i_t = 1.f / (1.f + expf(-sp[0][hh][bb]));
        const float f_t = 1.f / (1.f + expf(-sp[1][hh][bb]));
        const float g_t = tanhf(sp[2][hh][bb]);
        const float o_t = 1.f / (1.f + expf(-sp[3][hh][bb]));

        const float cv   = c0[(size_t)l * B_ * H_ + (size_t)bb * H_ + h];
        const float cnew = f_t * cv + i_t * g_t;
        const float hnew = o_t * tanhf(cnew);

        const size_t idx = (size_t)bb * H_ + h;
        out[(size_t)B_ * H_ * (1 + l) + idx] = hnew;   // h_t[l]
        out[(size_t)B_ * H_ * (3 + l) + idx] = cnew;   // c_t[l]
        if (l == 1)
            out[idx] = hnew;                           // out == h_t[1]
    }
}

// ---------------------------------------------------------------------------
extern "C" void kernel_launch(void* const* d_in, const int* in_sizes, int n_in,
                              void* d_out, int out_size)
{
    const float* input_seq = (const float*)d_in[0];
    const float* h0        = (const float*)d_in[1];
    const float* c0        = (const float*)d_in[2];
    const float* W_x       = (const float*)d_in[3];
    const float* W_h       = (const float*)d_in[4];
    const float* b_x       = (const float*)d_in[5];
    const float* b_h       = (const float*)d_in[6];
    const float* A_x       = (const float*)d_in[7];
    const float* B_x       = (const float*)d_in[8];
    const float* A_h       = (const float*)d_in[9];
    const float* B_h       = (const float*)d_in[10];
    float* out = (float*)d_out;

    const float* x_last = input_seq + (size_t)(T_ - 1) * B_ * I_;

    for (int l = 0; l < L_; ++l) {
        const float* x = (l == 0) ? x_last : (out + (size_t)B_ * H_);  // h_t[0]

        gemm_mma_kernel<<<dim3(N_TOT / MT, KS), 256>>>(x, h0, W_x, W_h,
                                                       A_x, A_h, B_x, B_h, l);
        gates_kernel<<<H_ / 2, 256>>>(b_x, b_h, c0, out, l);
    }
}